// round 1
// baseline (speedup 1.0000x reference)
#include <cuda_runtime.h>

// ---------------------------------------------------------------------------
// Problem constants
// ---------------------------------------------------------------------------
#define BB 4
#define TT 16
#define HH 64
#define WW 64
#define FF 64
#define CN 256            // 4*F gate channels
#define HW (HH*WW)        // 4096
#define HW3 (32*32)       // 1024

// Scratch (device globals: allocation-free rule)
__device__ float g_xz[(long long)BB*TT*HW*CN];   // 67,108,864 floats (256 MiB)
__device__ float g_z [(long long)BB*HW*CN];      // 4,194,304
__device__ float g_ha[(long long)BB*TT*HW*FF];   // 16,777,216
__device__ float g_h3[(long long)BB*TT*HW3*FF];  // 4,194,304
__device__ float g_c [(long long)BB*HW*FF];      // 1,048,576

typedef unsigned long long u64;

__device__ __forceinline__ u64 splat2(float a) {
    u64 r;
    asm("mov.b64 %0, {%1, %1};" : "=l"(r) : "r"(__float_as_uint(a)));
    return r;
}
__device__ __forceinline__ void ffma2(u64& acc, u64 a, u64 b) {
    asm("fma.rn.f32x2 %0, %1, %2, %0;" : "+l"(acc) : "l"(a), "l"(b));
}

// ---------------------------------------------------------------------------
// Implicit-GEMM conv kernel.
//   A: im2col gather of input  (M = n_img*Ho*Wo, K = KH*KH*Cin)
//   B: weights (K x 256) row-major  (exactly the (kh,kw,Cin,4F) layout)
//   C: out[img, p, n] (+ optional bias[n], + optional addend[img,p,n])
// Optional BN on the gathered input: v*(bns[ci]/sqrt(1.001)) + bnb[ci]
// Tiling: BM=128, BN=128, BK=16, 256 threads, 8x8 per thread, f32x2 FMAs.
// Requirements satisfied by this problem: M%128==0, Kdim%16==0, Cin%8==0.
// ---------------------------------------------------------------------------
#define BM 128
#define BNT 128
#define BK 16

template<int KH, int STRIDE>
__global__ void __launch_bounds__(256)
conv_gemm(const float* __restrict__ in, long long in_img_stride,
          const float* __restrict__ wgt,
          const float* __restrict__ bias,
          const float* __restrict__ bns, const float* __restrict__ bnb,
          const float* __restrict__ addend, long long add_img_stride,
          float* __restrict__ out, long long out_img_stride,
          int Hin, int Win, int Cin, int Ho, int Wo, int Kdim)
{
    constexpr int PAD = (KH - 1) / 2;
    const float BN_RS = 0.9995003746877732f;   // 1/sqrt(1+1e-3)

    __shared__ float As[BK][BM];
    __shared__ float Bs[BK][BNT];

    const int tid  = threadIdx.x;
    const int tx   = tid & 15;     // n subtile
    const int ty   = tid >> 4;     // m subtile
    const int nblk = blockIdx.x * BNT;
    const int mblk = blockIdx.y * BM;
    const int HoWo = Ho * Wo;

    // A-load mapping: row a_m, k range [a_k, a_k+8)
    const int a_m = tid & 127;
    const int a_k = (tid >> 7) * 8;
    {
        // nothing
    }
    const int m_g  = mblk + a_m;
    const int img_a = m_g / HoWo;
    const int p_a   = m_g - img_a * HoWo;
    const int oy    = p_a / Wo;
    const int ox    = p_a - oy * Wo;

    // B-load mapping
    const int b_k = tid >> 4;          // 0..15
    const int b_n = (tid & 15) * 8;    // 0..120

    u64 acc[8][4];
    #pragma unroll
    for (int i = 0; i < 8; i++)
        #pragma unroll
        for (int j = 0; j < 4; j++) acc[i][j] = 0ull;

    for (int kt = 0; kt < Kdim; kt += BK) {
        // ---- load A tile (implicit im2col gather) ----
        {
            const int kg = kt + a_k;
            const int ci = kg % Cin;          // kg multiple of 8, Cin multiple of 8
            const int r  = kg / Cin;
            const int kx = r % KH;
            const int ky = r / KH;
            const int iy = oy * STRIDE + ky - PAD;
            const int ix = ox * STRIDE + kx - PAD;
            const bool valid = ((unsigned)iy < (unsigned)Hin) &&
                               ((unsigned)ix < (unsigned)Win);
            float av[8];
            if (valid) {
                const float4* src = reinterpret_cast<const float4*>(
                    in + (long long)img_a * in_img_stride +
                    ((long long)iy * Win + ix) * Cin + ci);
                float4 v0 = src[0];
                float4 v1 = src[1];
                av[0]=v0.x; av[1]=v0.y; av[2]=v0.z; av[3]=v0.w;
                av[4]=v1.x; av[5]=v1.y; av[6]=v1.z; av[7]=v1.w;
                if (bns) {
                    #pragma unroll
                    for (int j = 0; j < 8; j++)
                        av[j] = av[j] * (__ldg(&bns[ci + j]) * BN_RS) + __ldg(&bnb[ci + j]);
                }
            } else {
                #pragma unroll
                for (int j = 0; j < 8; j++) av[j] = 0.f;
            }
            #pragma unroll
            for (int j = 0; j < 8; j++) As[a_k + j][a_m] = av[j];
        }
        // ---- load B tile (weights, contiguous) ----
        {
            const float4* wp = reinterpret_cast<const float4*>(
                wgt + (long long)(kt + b_k) * CN + nblk + b_n);
            *reinterpret_cast<float4*>(&Bs[b_k][b_n])     = wp[0];
            *reinterpret_cast<float4*>(&Bs[b_k][b_n + 4]) = wp[1];
        }
        __syncthreads();

        // ---- compute ----
        #pragma unroll
        for (int k = 0; k < BK; k++) {
            float4 a0 = *reinterpret_cast<const float4*>(&As[k][ty * 8]);
            float4 a1 = *reinterpret_cast<const float4*>(&As[k][ty * 8 + 4]);
            ulonglong2 b01 = *reinterpret_cast<const ulonglong2*>(&Bs[k][tx * 8]);
            ulonglong2 b23 = *reinterpret_cast<const ulonglong2*>(&Bs[k][tx * 8 + 4]);
            u64 bb[4] = { b01.x, b01.y, b23.x, b23.y };
            float aa[8] = { a0.x, a0.y, a0.z, a0.w, a1.x, a1.y, a1.z, a1.w };
            #pragma unroll
            for (int i = 0; i < 8; i++) {
                u64 as = splat2(aa[i]);
                #pragma unroll
                for (int j = 0; j < 4; j++) ffma2(acc[i][j], as, bb[j]);
            }
        }
        __syncthreads();
    }

    // ---- epilogue ----
    #pragma unroll
    for (int i = 0; i < 8; i++) {
        const int m   = mblk + ty * 8 + i;
        const int img = m / HoWo;
        const int p   = m - img * HoWo;
        const int ng  = nblk + tx * 8;
        float v[8];
        #pragma unroll
        for (int j = 0; j < 4; j++) {
            float2 f = *reinterpret_cast<float2*>(&acc[i][j]);
            v[2 * j] = f.x; v[2 * j + 1] = f.y;
        }
        if (bias) {
            #pragma unroll
            for (int j = 0; j < 8; j++) v[j] += __ldg(&bias[ng + j]);
        }
        if (addend) {
            const float4* ap = reinterpret_cast<const float4*>(
                addend + (long long)img * add_img_stride + (long long)p * CN + ng);
            float4 q0 = ap[0], q1 = ap[1];
            v[0]+=q0.x; v[1]+=q0.y; v[2]+=q0.z; v[3]+=q0.w;
            v[4]+=q1.x; v[5]+=q1.y; v[6]+=q1.z; v[7]+=q1.w;
        }
        float* op = out + (long long)img * out_img_stride + (long long)p * CN + ng;
        *reinterpret_cast<float4*>(op)     = make_float4(v[0], v[1], v[2], v[3]);
        *reinterpret_cast<float4*>(op + 4) = make_float4(v[4], v[5], v[6], v[7]);
    }
}

// ---------------------------------------------------------------------------
// LSTM gate kernel: z (img,pix,256) -> c,h   (hard-sigmoid gates, relu cell)
// ---------------------------------------------------------------------------
__device__ __forceinline__ float hsg(float x) {
    return fminf(fmaxf(fmaf(x, 0.2f, 0.5f), 0.f), 1.f);
}

__global__ void gate_kernel(const float* __restrict__ z, long long z_img_stride,
                            float* __restrict__ c,
                            float* __restrict__ hout, long long h_img_stride,
                            int HWp, int n_img, int first)
{
    const int idx = blockIdx.x * blockDim.x + threadIdx.x;
    const int total = n_img * HWp * (FF / 4);
    if (idx >= total) return;
    const int f4  = idx & 15;        // FF/4 == 16
    const int pp  = idx >> 4;
    const int pix = pp % HWp;
    const int img = pp / HWp;

    const float* zb = z + (long long)img * z_img_stride + (long long)pix * CN + f4 * 4;
    float4 zi = *reinterpret_cast<const float4*>(zb);
    float4 zf = *reinterpret_cast<const float4*>(zb + FF);
    float4 zc = *reinterpret_cast<const float4*>(zb + 2 * FF);
    float4 zo = *reinterpret_cast<const float4*>(zb + 3 * FF);

    const long long coff = ((long long)img * HWp + pix) * FF + f4 * 4;
    float4 cold = first ? make_float4(0.f, 0.f, 0.f, 0.f)
                        : *reinterpret_cast<const float4*>(c + coff);

    float4 cn, hh;
    cn.x = hsg(zf.x) * cold.x + hsg(zi.x) * fmaxf(zc.x, 0.f);
    cn.y = hsg(zf.y) * cold.y + hsg(zi.y) * fmaxf(zc.y, 0.f);
    cn.z = hsg(zf.z) * cold.z + hsg(zi.z) * fmaxf(zc.z, 0.f);
    cn.w = hsg(zf.w) * cold.w + hsg(zi.w) * fmaxf(zc.w, 0.f);
    hh.x = hsg(zo.x) * fmaxf(cn.x, 0.f);
    hh.y = hsg(zo.y) * fmaxf(cn.y, 0.f);
    hh.z = hsg(zo.z) * fmaxf(cn.z, 0.f);
    hh.w = hsg(zo.w) * fmaxf(cn.w, 0.f);

    *reinterpret_cast<float4*>(c + coff) = cn;
    float* hb = hout + (long long)img * h_img_stride + (long long)pix * FF + f4 * 4;
    *reinterpret_cast<float4*>(hb) = hh;
}

// ---------------------------------------------------------------------------
// Conv3D 3x3x3, 64 -> 1, 'SAME', + ReLU.  h3: (B,T,32,32,64), out: (B,T,32,32)
// ---------------------------------------------------------------------------
__global__ void conv3d_kernel(const float* __restrict__ h,
                              const float* __restrict__ w,
                              const float* __restrict__ b,
                              float* __restrict__ out)
{
    const int idx = blockIdx.x * blockDim.x + threadIdx.x;
    if (idx >= BB * TT * 32 * 32) return;
    const int x  = idx & 31;
    const int y  = (idx >> 5) & 31;
    const int t  = (idx >> 10) & 15;
    const int bb = idx >> 14;

    float acc = __ldg(&b[0]);
    #pragma unroll
    for (int dt = -1; dt <= 1; dt++) {
        const int ti = t + dt;
        if ((unsigned)ti >= (unsigned)TT) continue;
        #pragma unroll
        for (int dy = -1; dy <= 1; dy++) {
            const int yi = y + dy;
            if ((unsigned)yi >= 32u) continue;
            #pragma unroll
            for (int dx = -1; dx <= 1; dx++) {
                const int xi = x + dx;
                if ((unsigned)xi >= 32u) continue;
                const float4* hp = reinterpret_cast<const float4*>(
                    h + ((((long long)bb * TT + ti) * 32 + yi) * 32 + xi) * FF);
                const float4* wp = reinterpret_cast<const float4*>(
                    w + (((dt + 1) * 3 + (dy + 1)) * 3 + (dx + 1)) * FF);
                #pragma unroll
                for (int c4 = 0; c4 < FF / 4; c4++) {
                    float4 hv = hp[c4];
                    float4 wv = __ldg(&wp[c4]);
                    acc += hv.x * wv.x + hv.y * wv.y + hv.z * wv.z + hv.w * wv.w;
                }
            }
        }
    }
    out[idx] = fmaxf(acc, 0.f);
}

// ---------------------------------------------------------------------------
// Host launch helpers
// ---------------------------------------------------------------------------
template<int KH, int STRIDE>
static void conv_launch(const float* in, long long in_str,
                        const float* w, const float* bias,
                        const float* bns, const float* bnb,
                        const float* add, long long add_str,
                        float* out, long long out_str,
                        int Hin, int Win, int Cin, int Ho, int Wo, int n_img)
{
    const int Kdim = KH * KH * Cin;
    const int M = n_img * Ho * Wo;
    dim3 grid(CN / BNT, M / BM);
    conv_gemm<KH, STRIDE><<<grid, 256>>>(in, in_str, w, bias, bns, bnb,
                                         add, add_str, out, out_str,
                                         Hin, Win, Cin, Ho, Wo, Kdim);
}

static void gate_launch(const float* z, long long z_str, float* c,
                        float* hout, long long h_str, int HWp, int n_img, int first)
{
    const int total = n_img * HWp * (FF / 4);
    gate_kernel<<<(total + 255) / 256, 256>>>(z, z_str, c, hout, h_str, HWp, n_img, first);
}

extern "C" void kernel_launch(void* const* d_in, const int* in_sizes, int n_in,
                              void* d_out, int out_size)
{
    const float* x   = (const float*)d_in[0];
    const float* k1  = (const float*)d_in[1];
    const float* rk1 = (const float*)d_in[2];
    const float* b1  = (const float*)d_in[3];
    const float* g1  = (const float*)d_in[4];
    const float* be1 = (const float*)d_in[5];
    const float* k2  = (const float*)d_in[6];
    const float* rk2 = (const float*)d_in[7];
    const float* b2  = (const float*)d_in[8];
    const float* g2  = (const float*)d_in[9];
    const float* be2 = (const float*)d_in[10];
    const float* k3  = (const float*)d_in[11];
    const float* rk3 = (const float*)d_in[12];
    const float* b3  = (const float*)d_in[13];
    const float* w3d = (const float*)d_in[14];
    const float* b3d = (const float*)d_in[15];
    float* out = (float*)d_out;

    float *xz, *zb, *ha, *h3, *cc;
    cudaGetSymbolAddress((void**)&xz, g_xz);
    cudaGetSymbolAddress((void**)&zb, g_z);
    cudaGetSymbolAddress((void**)&ha, g_ha);
    cudaGetSymbolAddress((void**)&h3, g_h3);
    cudaGetSymbolAddress((void**)&cc, g_c);

    const long long X_IMG   = (long long)HW * 16;       // input x img stride (Cin=16)
    const long long XZ_IMG  = (long long)TT * HW * CN;   // xz stride over b
    const long long XZ_T    = (long long)HW * CN;        // xz stride over t
    const long long H_IMG   = (long long)TT * HW * FF;   // h stride over b
    const long long H_T     = (long long)HW * FF;        // h stride over t
    const long long Z_IMG   = (long long)HW * CN;
    const long long XZ3_IMG = (long long)TT * HW3 * CN;
    const long long XZ3_T   = (long long)HW3 * CN;
    const long long H3_IMG  = (long long)TT * HW3 * FF;
    const long long H3_T    = (long long)HW3 * FF;
    const long long Z3_IMG  = (long long)HW3 * CN;

    // ================= Layer 1: ConvLSTM 5x5, F=64, stride 1 =================
    // input conv for all (b,t)
    conv_launch<5, 1>(x, X_IMG, k1, b1, nullptr, nullptr, nullptr, 0,
                      xz, XZ_T, HH, WW, 16, HH, WW, BB * TT);
    // t = 0 (h_{-1} = 0)
    gate_launch(xz, XZ_IMG, cc, ha, H_IMG, HW, BB, 1);
    for (int t = 1; t < TT; t++) {
        conv_launch<5, 1>(ha + (long long)(t - 1) * H_T, H_IMG, rk1,
                          nullptr, nullptr, nullptr,
                          xz + (long long)t * XZ_T, XZ_IMG,
                          zb, Z_IMG, HH, WW, FF, HH, WW, BB);
        gate_launch(zb, Z_IMG, cc, ha + (long long)t * H_T, H_IMG, HW, BB, 0);
    }

    // ================= Layer 2: ConvLSTM 3x3, F=64, stride 1 (BN1 on input) ==
    conv_launch<3, 1>(ha, H_T, k2, b2, g1, be1, nullptr, 0,
                      xz, XZ_T, HH, WW, FF, HH, WW, BB * TT);
    gate_launch(xz, XZ_IMG, cc, ha, H_IMG, HW, BB, 1);   // overwrites h1[0] (done with it)
    for (int t = 1; t < TT; t++) {
        conv_launch<3, 1>(ha + (long long)(t - 1) * H_T, H_IMG, rk2,
                          nullptr, nullptr, nullptr,
                          xz + (long long)t * XZ_T, XZ_IMG,
                          zb, Z_IMG, HH, WW, FF, HH, WW, BB);
        gate_launch(zb, Z_IMG, cc, ha + (long long)t * H_T, H_IMG, HW, BB, 0);
    }

    // ================= Layer 3: ConvLSTM 1x1, F=64, stride 2 (BN2 on input) ==
    conv_launch<1, 2>(ha, H_T, k3, b3, g2, be2, nullptr, 0,
                      xz, XZ3_T, HH, WW, FF, 32, 32, BB * TT);
    gate_launch(xz, XZ3_IMG, cc, h3, H3_IMG, HW3, BB, 1);
    for (int t = 1; t < TT; t++) {
        conv_launch<1, 1>(h3 + (long long)(t - 1) * H3_T, H3_IMG, rk3,
                          nullptr, nullptr, nullptr,
                          xz + (long long)t * XZ3_T, XZ3_IMG,
                          zb, Z3_IMG, 32, 32, FF, 32, 32, BB);
        gate_launch(zb, Z3_IMG, cc, h3 + (long long)t * H3_T, H3_IMG, HW3, BB, 0);
    }

    // ================= Conv3D 3x3x3 -> 1 + ReLU ==============================
    conv3d_kernel<<<(BB * TT * 32 * 32 + 255) / 256, 256>>>(h3, w3d, b3d, out);
}

// round 2
// speedup vs baseline: 1.0003x; 1.0003x over previous
#include <cuda_runtime.h>

// ---------------------------------------------------------------------------
// Problem constants
// ---------------------------------------------------------------------------
#define BB 4
#define TT 16
#define HH 64
#define WW 64
#define FF 64
#define CN 256            // 4*F gate channels
#define HW (HH*WW)        // 4096
#define HW3 (32*32)       // 1024

// Scratch (device globals: allocation-free rule)
__device__ float g_xz[(long long)BB*TT*HW*CN];   // 67,108,864 floats (256 MiB)
__device__ float g_z [(long long)BB*HW*CN];      // 4,194,304
__device__ float g_ha[(long long)BB*TT*HW*FF];   // 16,777,216
__device__ float g_h3[(long long)BB*TT*HW3*FF];  // 4,194,304
__device__ float g_c [(long long)BB*HW*FF];      // 1,048,576

typedef unsigned long long u64;

__device__ __forceinline__ u64 splat2(float a) {
    u64 r;
    asm("mov.b64 %0, {%1, %1};" : "=l"(r) : "r"(__float_as_uint(a)));
    return r;
}
__device__ __forceinline__ void ffma2(u64& acc, u64 a, u64 b) {
    asm("fma.rn.f32x2 %0, %1, %2, %0;" : "+l"(acc) : "l"(a), "l"(b));
}

// ---------------------------------------------------------------------------
// Implicit-GEMM conv kernel.
//   A: im2col gather of input  (M = n_img*Ho*Wo, K = KH*KH*Cin)
//   B: weights (K x 256) row-major  (exactly the (kh,kw,Cin,4F) layout)
//   C: out[img, p, n] (+ optional bias[n], + optional addend[img,p,n])
// Optional BN on the gathered input: v*(bns[ci]/sqrt(1.001)) + bnb[ci]
// Tiling: BM=128, BN=128, BK=16, 256 threads, 8x8 per thread, f32x2 FMAs.
// Requirements satisfied by this problem: M%128==0, Kdim%16==0, Cin%8==0.
// ---------------------------------------------------------------------------
#define BM 128
#define BNT 128
#define BK 16

template<int KH, int STRIDE>
__global__ void __launch_bounds__(256)
conv_gemm(const float* __restrict__ in, long long in_img_stride,
          const float* __restrict__ wgt,
          const float* __restrict__ bias,
          const float* __restrict__ bns, const float* __restrict__ bnb,
          const float* __restrict__ addend, long long add_img_stride,
          float* __restrict__ out, long long out_img_stride,
          int Hin, int Win, int Cin, int Ho, int Wo, int Kdim)
{
    constexpr int PAD = (KH - 1) / 2;
    const float BN_RS = 0.9995003746877732f;   // 1/sqrt(1+1e-3)

    __shared__ float As[BK][BM];
    __shared__ float Bs[BK][BNT];

    const int tid  = threadIdx.x;
    const int tx   = tid & 15;     // n subtile
    const int ty   = tid >> 4;     // m subtile
    const int nblk = blockIdx.x * BNT;
    const int mblk = blockIdx.y * BM;
    const int HoWo = Ho * Wo;

    // A-load mapping: row a_m, k range [a_k, a_k+8)
    const int a_m = tid & 127;
    const int a_k = (tid >> 7) * 8;
    {
        // nothing
    }
    const int m_g  = mblk + a_m;
    const int img_a = m_g / HoWo;
    const int p_a   = m_g - img_a * HoWo;
    const int oy    = p_a / Wo;
    const int ox    = p_a - oy * Wo;

    // B-load mapping
    const int b_k = tid >> 4;          // 0..15
    const int b_n = (tid & 15) * 8;    // 0..120

    u64 acc[8][4];
    #pragma unroll
    for (int i = 0; i < 8; i++)
        #pragma unroll
        for (int j = 0; j < 4; j++) acc[i][j] = 0ull;

    for (int kt = 0; kt < Kdim; kt += BK) {
        // ---- load A tile (implicit im2col gather) ----
        {
            const int kg = kt + a_k;
            const int ci = kg % Cin;          // kg multiple of 8, Cin multiple of 8
            const int r  = kg / Cin;
            const int kx = r % KH;
            const int ky = r / KH;
            const int iy = oy * STRIDE + ky - PAD;
            const int ix = ox * STRIDE + kx - PAD;
            const bool valid = ((unsigned)iy < (unsigned)Hin) &&
                               ((unsigned)ix < (unsigned)Win);
            float av[8];
            if (valid) {
                const float4* src = reinterpret_cast<const float4*>(
                    in + (long long)img_a * in_img_stride +
                    ((long long)iy * Win + ix) * Cin + ci);
                float4 v0 = src[0];
                float4 v1 = src[1];
                av[0]=v0.x; av[1]=v0.y; av[2]=v0.z; av[3]=v0.w;
                av[4]=v1.x; av[5]=v1.y; av[6]=v1.z; av[7]=v1.w;
                if (bns) {
                    #pragma unroll
                    for (int j = 0; j < 8; j++)
                        av[j] = av[j] * (__ldg(&bns[ci + j]) * BN_RS) + __ldg(&bnb[ci + j]);
                }
            } else {
                #pragma unroll
                for (int j = 0; j < 8; j++) av[j] = 0.f;
            }
            #pragma unroll
            for (int j = 0; j < 8; j++) As[a_k + j][a_m] = av[j];
        }
        // ---- load B tile (weights, contiguous) ----
        {
            const float4* wp = reinterpret_cast<const float4*>(
                wgt + (long long)(kt + b_k) * CN + nblk + b_n);
            *reinterpret_cast<float4*>(&Bs[b_k][b_n])     = wp[0];
            *reinterpret_cast<float4*>(&Bs[b_k][b_n + 4]) = wp[1];
        }
        __syncthreads();

        // ---- compute ----
        #pragma unroll
        for (int k = 0; k < BK; k++) {
            float4 a0 = *reinterpret_cast<const float4*>(&As[k][ty * 8]);
            float4 a1 = *reinterpret_cast<const float4*>(&As[k][ty * 8 + 4]);
            ulonglong2 b01 = *reinterpret_cast<const ulonglong2*>(&Bs[k][tx * 8]);
            ulonglong2 b23 = *reinterpret_cast<const ulonglong2*>(&Bs[k][tx * 8 + 4]);
            u64 bb[4] = { b01.x, b01.y, b23.x, b23.y };
            float aa[8] = { a0.x, a0.y, a0.z, a0.w, a1.x, a1.y, a1.z, a1.w };
            #pragma unroll
            for (int i = 0; i < 8; i++) {
                u64 as = splat2(aa[i]);
                #pragma unroll
                for (int j = 0; j < 4; j++) ffma2(acc[i][j], as, bb[j]);
            }
        }
        __syncthreads();
    }

    // ---- epilogue ----
    #pragma unroll
    for (int i = 0; i < 8; i++) {
        const int m   = mblk + ty * 8 + i;
        const int img = m / HoWo;
        const int p   = m - img * HoWo;
        const int ng  = nblk + tx * 8;
        float v[8];
        #pragma unroll
        for (int j = 0; j < 4; j++) {
            float2 f = *reinterpret_cast<float2*>(&acc[i][j]);
            v[2 * j] = f.x; v[2 * j + 1] = f.y;
        }
        if (bias) {
            #pragma unroll
            for (int j = 0; j < 8; j++) v[j] += __ldg(&bias[ng + j]);
        }
        if (addend) {
            const float4* ap = reinterpret_cast<const float4*>(
                addend + (long long)img * add_img_stride + (long long)p * CN + ng);
            float4 q0 = ap[0], q1 = ap[1];
            v[0]+=q0.x; v[1]+=q0.y; v[2]+=q0.z; v[3]+=q0.w;
            v[4]+=q1.x; v[5]+=q1.y; v[6]+=q1.z; v[7]+=q1.w;
        }
        float* op = out + (long long)img * out_img_stride + (long long)p * CN + ng;
        *reinterpret_cast<float4*>(op)     = make_float4(v[0], v[1], v[2], v[3]);
        *reinterpret_cast<float4*>(op + 4) = make_float4(v[4], v[5], v[6], v[7]);
    }
}

// ---------------------------------------------------------------------------
// LSTM gate kernel: z (img,pix,256) -> c,h   (hard-sigmoid gates, relu cell)
// ---------------------------------------------------------------------------
__device__ __forceinline__ float hsg(float x) {
    return fminf(fmaxf(fmaf(x, 0.2f, 0.5f), 0.f), 1.f);
}

__global__ void gate_kernel(const float* __restrict__ z, long long z_img_stride,
                            float* __restrict__ c,
                            float* __restrict__ hout, long long h_img_stride,
                            int HWp, int n_img, int first)
{
    const int idx = blockIdx.x * blockDim.x + threadIdx.x;
    const int total = n_img * HWp * (FF / 4);
    if (idx >= total) return;
    const int f4  = idx & 15;        // FF/4 == 16
    const int pp  = idx >> 4;
    const int pix = pp % HWp;
    const int img = pp / HWp;

    const float* zb = z + (long long)img * z_img_stride + (long long)pix * CN + f4 * 4;
    float4 zi = *reinterpret_cast<const float4*>(zb);
    float4 zf = *reinterpret_cast<const float4*>(zb + FF);
    float4 zc = *reinterpret_cast<const float4*>(zb + 2 * FF);
    float4 zo = *reinterpret_cast<const float4*>(zb + 3 * FF);

    const long long coff = ((long long)img * HWp + pix) * FF + f4 * 4;
    float4 cold = first ? make_float4(0.f, 0.f, 0.f, 0.f)
                        : *reinterpret_cast<const float4*>(c + coff);

    float4 cn, hh;
    cn.x = hsg(zf.x) * cold.x + hsg(zi.x) * fmaxf(zc.x, 0.f);
    cn.y = hsg(zf.y) * cold.y + hsg(zi.y) * fmaxf(zc.y, 0.f);
    cn.z = hsg(zf.z) * cold.z + hsg(zi.z) * fmaxf(zc.z, 0.f);
    cn.w = hsg(zf.w) * cold.w + hsg(zi.w) * fmaxf(zc.w, 0.f);
    hh.x = hsg(zo.x) * fmaxf(cn.x, 0.f);
    hh.y = hsg(zo.y) * fmaxf(cn.y, 0.f);
    hh.z = hsg(zo.z) * fmaxf(cn.z, 0.f);
    hh.w = hsg(zo.w) * fmaxf(cn.w, 0.f);

    *reinterpret_cast<float4*>(c + coff) = cn;
    float* hb = hout + (long long)img * h_img_stride + (long long)pix * FF + f4 * 4;
    *reinterpret_cast<float4*>(hb) = hh;
}

// ---------------------------------------------------------------------------
// Conv3D 3x3x3, 64 -> 1, 'SAME', + ReLU.  h3: (B,T,32,32,64), out: (B,T,32,32)
// ---------------------------------------------------------------------------
__global__ void conv3d_kernel(const float* __restrict__ h,
                              const float* __restrict__ w,
                              const float* __restrict__ b,
                              float* __restrict__ out)
{
    const int idx = blockIdx.x * blockDim.x + threadIdx.x;
    if (idx >= BB * TT * 32 * 32) return;
    const int x  = idx & 31;
    const int y  = (idx >> 5) & 31;
    const int t  = (idx >> 10) & 15;
    const int bb = idx >> 14;

    float acc = __ldg(&b[0]);
    #pragma unroll
    for (int dt = -1; dt <= 1; dt++) {
        const int ti = t + dt;
        if ((unsigned)ti >= (unsigned)TT) continue;
        #pragma unroll
        for (int dy = -1; dy <= 1; dy++) {
            const int yi = y + dy;
            if ((unsigned)yi >= 32u) continue;
            #pragma unroll
            for (int dx = -1; dx <= 1; dx++) {
                const int xi = x + dx;
                if ((unsigned)xi >= 32u) continue;
                const float4* hp = reinterpret_cast<const float4*>(
                    h + ((((long long)bb * TT + ti) * 32 + yi) * 32 + xi) * FF);
                const float4* wp = reinterpret_cast<const float4*>(
                    w + (((dt + 1) * 3 + (dy + 1)) * 3 + (dx + 1)) * FF);
                #pragma unroll
                for (int c4 = 0; c4 < FF / 4; c4++) {
                    float4 hv = hp[c4];
                    float4 wv = __ldg(&wp[c4]);
                    acc += hv.x * wv.x + hv.y * wv.y + hv.z * wv.z + hv.w * wv.w;
                }
            }
        }
    }
    out[idx] = fmaxf(acc, 0.f);
}

// ---------------------------------------------------------------------------
// Host launch helpers
// ---------------------------------------------------------------------------
template<int KH, int STRIDE>
static void conv_launch(const float* in, long long in_str,
                        const float* w, const float* bias,
                        const float* bns, const float* bnb,
                        const float* add, long long add_str,
                        float* out, long long out_str,
                        int Hin, int Win, int Cin, int Ho, int Wo, int n_img)
{
    const int Kdim = KH * KH * Cin;
    const int M = n_img * Ho * Wo;
    dim3 grid(CN / BNT, M / BM);
    conv_gemm<KH, STRIDE><<<grid, 256>>>(in, in_str, w, bias, bns, bnb,
                                         add, add_str, out, out_str,
                                         Hin, Win, Cin, Ho, Wo, Kdim);
}

static void gate_launch(const float* z, long long z_str, float* c,
                        float* hout, long long h_str, int HWp, int n_img, int first)
{
    const int total = n_img * HWp * (FF / 4);
    gate_kernel<<<(total + 255) / 256, 256>>>(z, z_str, c, hout, h_str, HWp, n_img, first);
}

extern "C" void kernel_launch(void* const* d_in, const int* in_sizes, int n_in,
                              void* d_out, int out_size)
{
    const float* x   = (const float*)d_in[0];
    const float* k1  = (const float*)d_in[1];
    const float* rk1 = (const float*)d_in[2];
    const float* b1  = (const float*)d_in[3];
    const float* g1  = (const float*)d_in[4];
    const float* be1 = (const float*)d_in[5];
    const float* k2  = (const float*)d_in[6];
    const float* rk2 = (const float*)d_in[7];
    const float* b2  = (const float*)d_in[8];
    const float* g2  = (const float*)d_in[9];
    const float* be2 = (const float*)d_in[10];
    const float* k3  = (const float*)d_in[11];
    const float* rk3 = (const float*)d_in[12];
    const float* b3  = (const float*)d_in[13];
    const float* w3d = (const float*)d_in[14];
    const float* b3d = (const float*)d_in[15];
    float* out = (float*)d_out;

    float *xz, *zb, *ha, *h3, *cc;
    cudaGetSymbolAddress((void**)&xz, g_xz);
    cudaGetSymbolAddress((void**)&zb, g_z);
    cudaGetSymbolAddress((void**)&ha, g_ha);
    cudaGetSymbolAddress((void**)&h3, g_h3);
    cudaGetSymbolAddress((void**)&cc, g_c);

    const long long X_IMG   = (long long)HW * 16;       // input x img stride (Cin=16)
    const long long XZ_IMG  = (long long)TT * HW * CN;   // xz stride over b
    const long long XZ_T    = (long long)HW * CN;        // xz stride over t
    const long long H_IMG   = (long long)TT * HW * FF;   // h stride over b
    const long long H_T     = (long long)HW * FF;        // h stride over t
    const long long Z_IMG   = (long long)HW * CN;
    const long long XZ3_IMG = (long long)TT * HW3 * CN;
    const long long XZ3_T   = (long long)HW3 * CN;
    const long long H3_IMG  = (long long)TT * HW3 * FF;
    const long long H3_T    = (long long)HW3 * FF;
    const long long Z3_IMG  = (long long)HW3 * CN;

    // ================= Layer 1: ConvLSTM 5x5, F=64, stride 1 =================
    // input conv for all (b,t)
    conv_launch<5, 1>(x, X_IMG, k1, b1, nullptr, nullptr, nullptr, 0,
                      xz, XZ_T, HH, WW, 16, HH, WW, BB * TT);
    // t = 0 (h_{-1} = 0)
    gate_launch(xz, XZ_IMG, cc, ha, H_IMG, HW, BB, 1);
    for (int t = 1; t < TT; t++) {
        conv_launch<5, 1>(ha + (long long)(t - 1) * H_T, H_IMG, rk1,
                          nullptr, nullptr, nullptr,
                          xz + (long long)t * XZ_T, XZ_IMG,
                          zb, Z_IMG, HH, WW, FF, HH, WW, BB);
        gate_launch(zb, Z_IMG, cc, ha + (long long)t * H_T, H_IMG, HW, BB, 0);
    }

    // ================= Layer 2: ConvLSTM 3x3, F=64, stride 1 (BN1 on input) ==
    conv_launch<3, 1>(ha, H_T, k2, b2, g1, be1, nullptr, 0,
                      xz, XZ_T, HH, WW, FF, HH, WW, BB * TT);
    gate_launch(xz, XZ_IMG, cc, ha, H_IMG, HW, BB, 1);   // overwrites h1[0] (done with it)
    for (int t = 1; t < TT; t++) {
        conv_launch<3, 1>(ha + (long long)(t - 1) * H_T, H_IMG, rk2,
                          nullptr, nullptr, nullptr,
                          xz + (long long)t * XZ_T, XZ_IMG,
                          zb, Z_IMG, HH, WW, FF, HH, WW, BB);
        gate_launch(zb, Z_IMG, cc, ha + (long long)t * H_T, H_IMG, HW, BB, 0);
    }

    // ================= Layer 3: ConvLSTM 1x1, F=64, stride 2 (BN2 on input) ==
    conv_launch<1, 2>(ha, H_T, k3, b3, g2, be2, nullptr, 0,
                      xz, XZ3_T, HH, WW, FF, 32, 32, BB * TT);
    gate_launch(xz, XZ3_IMG, cc, h3, H3_IMG, HW3, BB, 1);
    for (int t = 1; t < TT; t++) {
        conv_launch<1, 1>(h3 + (long long)(t - 1) * H3_T, H3_IMG, rk3,
                          nullptr, nullptr, nullptr,
                          xz + (long long)t * XZ3_T, XZ3_IMG,
                          zb, Z3_IMG, 32, 32, FF, 32, 32, BB);
        gate_launch(zb, Z3_IMG, cc, h3 + (long long)t * H3_T, H3_IMG, HW3, BB, 0);
    }

    // ================= Conv3D 3x3x3 -> 1 + ReLU ==============================
    conv3d_kernel<<<(BB * TT * 32 * 32 + 255) / 256, 256>>>(h3, w3d, b3d, out);
}